// round 1
// baseline (speedup 1.0000x reference)
#include <cuda_runtime.h>
#include <math.h>

#define B_   32
#define T_   512
#define IND  512
#define U_   1024
#define G4   4096   // 4*U

// ---------------- scratch (static device globals; no allocs allowed) ----------
__device__ __align__(16) float g_xproj[(size_t)B_ * T_ * G4];  // 256 MB: [b][t][4U]
__device__ __align__(16) float g_h[2][U_ * B_];                // ping-pong hT: [u][b]
__device__ __align__(16) float g_c[U_ * B_];                   // cT: [u][b]

// ---------------- init: zero h0, c0 every launch (graph replays) --------------
__global__ void init_state() {
    int i = blockIdx.x * blockDim.x + threadIdx.x;
    if (i < U_ * B_) { g_h[0][i] = 0.f; g_c[i] = 0.f; }
}

// ---------------- Kernel 1: x_proj = data @ Wx + b ----------------------------
// A [16384][512] row-major, B [512][4096] row-major, C -> g_xproj [16384][4096]
__global__ __launch_bounds__(256) void gemm_xproj(
    const float* __restrict__ A, const float* __restrict__ Bw,
    const float* __restrict__ bias)
{
    const int K = IND, N = G4;
    __shared__ float As[16][132];   // transposed A tile, padded
    __shared__ float Bs[16][128];

    int tid = threadIdx.x;
    int bm = blockIdx.y * 128;
    int bn = blockIdx.x * 128;

    int ty = tid >> 4;          // 0..15
    int tx = tid & 15;          // 0..15

    int arow = tid >> 2;        // 0..63
    int acol = (tid & 3) * 4;   // 0,4,8,12
    int brow = tid >> 5;        // 0..7
    int bcol = (tid & 31) * 4;  // 0..124

    const float* Aptr = A + (size_t)(bm + arow) * K + acol;
    const float* Bptr = Bw + (size_t)brow * N + bn + bcol;

    float acc[8][8];
    #pragma unroll
    for (int i = 0; i < 8; i++)
        #pragma unroll
        for (int j = 0; j < 8; j++) acc[i][j] = 0.f;

    for (int k0 = 0; k0 < K; k0 += 16) {
        float4 a0 = *(const float4*)(Aptr);
        float4 a1 = *(const float4*)(Aptr + (size_t)64 * K);
        float4 b0 = *(const float4*)(Bptr);
        float4 b1 = *(const float4*)(Bptr + (size_t)8 * N);

        As[acol + 0][arow] = a0.x; As[acol + 1][arow] = a0.y;
        As[acol + 2][arow] = a0.z; As[acol + 3][arow] = a0.w;
        As[acol + 0][arow + 64] = a1.x; As[acol + 1][arow + 64] = a1.y;
        As[acol + 2][arow + 64] = a1.z; As[acol + 3][arow + 64] = a1.w;
        *(float4*)&Bs[brow][bcol]     = b0;
        *(float4*)&Bs[brow + 8][bcol] = b1;
        __syncthreads();

        #pragma unroll
        for (int kk = 0; kk < 16; kk++) {
            float a[8], b[8];
            *(float4*)&a[0] = *(const float4*)&As[kk][ty * 8];
            *(float4*)&a[4] = *(const float4*)&As[kk][ty * 8 + 4];
            *(float4*)&b[0] = *(const float4*)&Bs[kk][tx * 8];
            *(float4*)&b[4] = *(const float4*)&Bs[kk][tx * 8 + 4];
            #pragma unroll
            for (int i = 0; i < 8; i++)
                #pragma unroll
                for (int j = 0; j < 8; j++)
                    acc[i][j] = fmaf(a[i], b[j], acc[i][j]);
        }
        __syncthreads();
        Aptr += 16;
        Bptr += (size_t)16 * N;
    }

    float bv[8];
    #pragma unroll
    for (int j = 0; j < 8; j++) bv[j] = bias[bn + tx * 8 + j];

    #pragma unroll
    for (int i = 0; i < 8; i++) {
        float* crow = g_xproj + (size_t)(bm + ty * 8 + i) * N + bn + tx * 8;
        float4 v0 = make_float4(acc[i][0] + bv[0], acc[i][1] + bv[1],
                                acc[i][2] + bv[2], acc[i][3] + bv[3]);
        float4 v1 = make_float4(acc[i][4] + bv[4], acc[i][5] + bv[5],
                                acc[i][6] + bv[6], acc[i][7] + bv[7]);
        *(float4*)crow       = v0;
        *(float4*)(crow + 4) = v1;
    }
}

// ---------------- Kernel 2: one LSTM timestep ---------------------------------
// 128 blocks x 128 threads. Block owns 8 units; warp q computes gate q for those
// 8 units x 32 batches (lane = batch). Fused elementwise epilogue.
__device__ __forceinline__ float sigmoidf_(float x) {
    return 1.f / (1.f + __expf(-x));
}

__global__ __launch_bounds__(128) void lstm_step(
    const float* __restrict__ Wh,   // [1024][4096]
    float* __restrict__ out,        // [32][512][1024]
    int t)
{
    __shared__ float hs[64][32];       // 8 KB: h chunk [k][b]
    __shared__ float ws[64][32];       // 8 KB: Wh chunk [k][q*8+j]
    __shared__ float gs[4][8][32];     // 4 KB: gates [q][u][b]

    const int tid  = threadIdx.x;
    const int lane = tid & 31;
    const int q    = tid >> 5;                 // gate id 0..3 (i,f,g,o)
    const int u0   = blockIdx.x * 8;
    const int cbase = q * U_ + u0;             // Wh column base for this warp

    const float* __restrict__ h_in = g_h[t & 1];
    float* __restrict__ h_out      = g_h[(t + 1) & 1];

    float acc[8];
    #pragma unroll
    for (int j = 0; j < 8; j++) acc[j] = 0.f;

    for (int k0 = 0; k0 < U_; k0 += 64) {
        // stage h chunk: 2048 floats = 512 float4
        #pragma unroll
        for (int i = 0; i < 4; i++) {
            int f = tid + i * 128;
            ((float4*)hs)[f] = ((const float4*)(h_in + k0 * B_))[f];
        }
        // stage Wh chunk: 64 rows x 4 strips x 8 floats
        #pragma unroll
        for (int i = 0; i < 4; i++) {
            int f  = tid + i * 128;           // float4 index 0..511
            int k  = f >> 3;                  // 0..63
            int r  = f & 7;
            int s  = r >> 1;                  // strip (gate) 0..3
            int hf = r & 1;                   // half of 8-float strip
            float4 v = *(const float4*)(Wh + (size_t)(k0 + k) * G4 + s * U_ + u0 + hf * 4);
            *(float4*)&ws[k][s * 8 + hf * 4] = v;
        }
        __syncthreads();

        #pragma unroll
        for (int kk = 0; kk < 64; kk++) {
            float a = hs[kk][lane];
            float4 w0 = *(const float4*)&ws[kk][q * 8];
            float4 w1 = *(const float4*)&ws[kk][q * 8 + 4];
            acc[0] = fmaf(a, w0.x, acc[0]);
            acc[1] = fmaf(a, w0.y, acc[1]);
            acc[2] = fmaf(a, w0.z, acc[2]);
            acc[3] = fmaf(a, w0.w, acc[3]);
            acc[4] = fmaf(a, w1.x, acc[4]);
            acc[5] = fmaf(a, w1.y, acc[5]);
            acc[6] = fmaf(a, w1.z, acc[6]);
            acc[7] = fmaf(a, w1.w, acc[7]);
        }
        __syncthreads();
    }

    // add x_proj (coalesced per lane: 8 contiguous floats) and publish gates
    {
        const float* xp = g_xproj + ((size_t)lane * T_ + t) * G4 + cbase;
        float4 x0 = *(const float4*)xp;
        float4 x1 = *(const float4*)(xp + 4);
        gs[q][0][lane] = acc[0] + x0.x;
        gs[q][1][lane] = acc[1] + x0.y;
        gs[q][2][lane] = acc[2] + x0.z;
        gs[q][3][lane] = acc[3] + x0.w;
        gs[q][4][lane] = acc[4] + x1.x;
        gs[q][5][lane] = acc[5] + x1.y;
        gs[q][6][lane] = acc[6] + x1.z;
        gs[q][7][lane] = acc[7] + x1.w;
    }
    __syncthreads();

    // elementwise LSTM update: 8 units x 32 batches = 256 pairs, 2 per thread
    #pragma unroll
    for (int p = tid; p < 256; p += 128) {
        int u = p >> 5;
        int b = p & 31;
        float ig = sigmoidf_(gs[0][u][b]);
        float fg = sigmoidf_(gs[1][u][b]);
        float gg = tanhf(gs[2][u][b]);
        float og = sigmoidf_(gs[3][u][b]);
        int uu = u0 + u;
        float cold = g_c[uu * B_ + b];
        float cn = fg * cold + ig * gg;
        g_c[uu * B_ + b] = cn;
        float h = og * tanhf(cn);
        h_out[uu * B_ + b] = h;
        out[((size_t)b * T_ + t) * U_ + uu] = h;
    }
}

// ---------------- launch ------------------------------------------------------
extern "C" void kernel_launch(void* const* d_in, const int* in_sizes, int n_in,
                              void* d_out, int out_size) {
    const float* data = (const float*)d_in[0];   // [32,512,512]
    const float* Wx   = (const float*)d_in[1];   // [512,4096]
    const float* Wh   = (const float*)d_in[2];   // [1024,4096]
    const float* bias = (const float*)d_in[3];   // [4096]
    float* out = (float*)d_out;                  // [32,512,1024]

    init_state<<<32, 1024>>>();

    dim3 grid(G4 / 128, (B_ * T_) / 128);        // 32 x 128
    gemm_xproj<<<grid, 256>>>(data, Wx, bias);

    for (int t = 0; t < T_; t++)
        lstm_step<<<128, 128>>>(Wh, out, t);
}

// round 2
// speedup vs baseline: 1.1121x; 1.1121x over previous
#include <cuda_runtime.h>
#include <math.h>

#define B_   32
#define T_   512
#define IND  512
#define U_   1024
#define G4   4096   // 4*U

// ---------------- scratch (static device globals; no allocs allowed) ----------
__device__ __align__(16) float g_xproj[(size_t)B_ * T_ * G4];  // 256 MB: [b*T+t][4U]
__device__ __align__(16) float g_h[2][U_ * B_];                // ping-pong hT: [u][b]
__device__ __align__(16) float g_c[U_ * B_];                   // cT: [u][b]

// ---------------- init: zero h0, c0 every launch (graph replays) --------------
__global__ void init_state() {
    int i = blockIdx.x * blockDim.x + threadIdx.x;
    if (i < U_ * B_) { g_h[0][i] = 0.f; g_c[i] = 0.f; }
}

// ---------------- Kernel 1: x_proj = data @ Wx + b ----------------------------
__global__ __launch_bounds__(256) void gemm_xproj(
    const float* __restrict__ A, const float* __restrict__ Bw,
    const float* __restrict__ bias)
{
    const int K = IND, N = G4;
    __shared__ float As[16][132];
    __shared__ float Bs[16][128];

    int tid = threadIdx.x;
    int bm = blockIdx.y * 128;
    int bn = blockIdx.x * 128;

    int ty = tid >> 4;
    int tx = tid & 15;

    int arow = tid >> 2;
    int acol = (tid & 3) * 4;
    int brow = tid >> 5;
    int bcol = (tid & 31) * 4;

    const float* Aptr = A + (size_t)(bm + arow) * K + acol;
    const float* Bptr = Bw + (size_t)brow * N + bn + bcol;

    float acc[8][8];
    #pragma unroll
    for (int i = 0; i < 8; i++)
        #pragma unroll
        for (int j = 0; j < 8; j++) acc[i][j] = 0.f;

    for (int k0 = 0; k0 < K; k0 += 16) {
        float4 a0 = *(const float4*)(Aptr);
        float4 a1 = *(const float4*)(Aptr + (size_t)64 * K);
        float4 b0 = *(const float4*)(Bptr);
        float4 b1 = *(const float4*)(Bptr + (size_t)8 * N);

        As[acol + 0][arow] = a0.x; As[acol + 1][arow] = a0.y;
        As[acol + 2][arow] = a0.z; As[acol + 3][arow] = a0.w;
        As[acol + 0][arow + 64] = a1.x; As[acol + 1][arow + 64] = a1.y;
        As[acol + 2][arow + 64] = a1.z; As[acol + 3][arow + 64] = a1.w;
        *(float4*)&Bs[brow][bcol]     = b0;
        *(float4*)&Bs[brow + 8][bcol] = b1;
        __syncthreads();

        #pragma unroll
        for (int kk = 0; kk < 16; kk++) {
            float a[8], b[8];
            *(float4*)&a[0] = *(const float4*)&As[kk][ty * 8];
            *(float4*)&a[4] = *(const float4*)&As[kk][ty * 8 + 4];
            *(float4*)&b[0] = *(const float4*)&Bs[kk][tx * 8];
            *(float4*)&b[4] = *(const float4*)&Bs[kk][tx * 8 + 4];
            #pragma unroll
            for (int i = 0; i < 8; i++)
                #pragma unroll
                for (int j = 0; j < 8; j++)
                    acc[i][j] = fmaf(a[i], b[j], acc[i][j]);
        }
        __syncthreads();
        Aptr += 16;
        Bptr += (size_t)16 * N;
    }

    float bv[8];
    #pragma unroll
    for (int j = 0; j < 8; j++) bv[j] = bias[bn + tx * 8 + j];

    #pragma unroll
    for (int i = 0; i < 8; i++) {
        float* crow = g_xproj + (size_t)(bm + ty * 8 + i) * N + bn + tx * 8;
        float4 v0 = make_float4(acc[i][0] + bv[0], acc[i][1] + bv[1],
                                acc[i][2] + bv[2], acc[i][3] + bv[3]);
        float4 v1 = make_float4(acc[i][4] + bv[4], acc[i][5] + bv[5],
                                acc[i][6] + bv[6], acc[i][7] + bv[7]);
        *(float4*)crow       = v0;
        *(float4*)(crow + 4) = v1;
    }
}

// ---------------- Kernel 2: one LSTM timestep ---------------------------------
// 128 blocks x 256 threads (8 warps). Block owns 8 units x 4 gates x 32 batches.
// Warp w reduces K-chunk [w*128, w*128+128). Lane: g = lane&3 (gate),
// tb = lane>>2 (batch group of 4). Thread: 8 units x 4 batches = 32 accs.
// All operands via LDG (L2-resident Wh/h), no mid-loop syncs. Partials reduced
// through padded smem, fused activation epilogue.
__device__ __forceinline__ float sigmoidf_(float x) {
    return 1.f / (1.f + __expf(-x));
}

__global__ __launch_bounds__(256) void lstm_step(
    const float* __restrict__ Wh,   // [1024][4096]
    float* __restrict__ out,        // [32][512][1024]
    int t)
{
    __shared__ __align__(16) float part[8][4][8][36];  // [warp][gate][unit][batch+pad]

    const int tid  = threadIdx.x;
    const int w    = tid >> 5;
    const int lane = tid & 31;
    const int g    = lane & 3;        // gate
    const int tb   = lane >> 2;       // batch group (4 batches)
    const int u0   = blockIdx.x * 8;

    const float* __restrict__ h_in = g_h[t & 1];
    float* __restrict__ h_out      = g_h[(t + 1) & 1];

    const float* wp = Wh + (size_t)(w * 128) * G4 + g * U_ + u0;
    const float* hp = h_in + (w * 128) * B_ + tb * 4;

    float acc[8][4];
    #pragma unroll
    for (int u = 0; u < 8; u++)
        #pragma unroll
        for (int j = 0; j < 4; j++) acc[u][j] = 0.f;

    #pragma unroll 4
    for (int k = 0; k < 128; k++) {
        float4 w0 = *(const float4*)(wp);
        float4 w1 = *(const float4*)(wp + 4);
        float4 hv = *(const float4*)(hp);
        float wv[8] = {w0.x, w0.y, w0.z, w0.w, w1.x, w1.y, w1.z, w1.w};
        #pragma unroll
        for (int u = 0; u < 8; u++) {
            acc[u][0] = fmaf(wv[u], hv.x, acc[u][0]);
            acc[u][1] = fmaf(wv[u], hv.y, acc[u][1]);
            acc[u][2] = fmaf(wv[u], hv.z, acc[u][2]);
            acc[u][3] = fmaf(wv[u], hv.w, acc[u][3]);
        }
        wp += G4;
        hp += B_;
    }

    // publish partials (conflict-free: bank = (4u + b) & 31 within a warp)
    #pragma unroll
    for (int u = 0; u < 8; u++)
        *(float4*)&part[w][g][u][tb * 4] =
            make_float4(acc[u][0], acc[u][1], acc[u][2], acc[u][3]);
    __syncthreads();

    // epilogue: thread = (b, u); u fastest for coalesced xproj/out access
    const int b = tid >> 3;
    const int u = tid & 7;

    float gate[4];
    #pragma unroll
    for (int gg2 = 0; gg2 < 4; gg2++) {
        float s = 0.f;
        #pragma unroll
        for (int w2 = 0; w2 < 8; w2++) s += part[w2][gg2][u][b];
        gate[gg2] = s;
    }

    const float* xp = g_xproj + ((size_t)b * T_ + t) * G4 + u0 + u;
    gate[0] += xp[0];
    gate[1] += xp[U_];
    gate[2] += xp[2 * U_];
    gate[3] += xp[3 * U_];

    float ig = sigmoidf_(gate[0]);
    float fg = sigmoidf_(gate[1]);
    float gv = tanhf(gate[2]);
    float og = sigmoidf_(gate[3]);

    const int ci = (u0 + u) * B_ + b;
    float cn = fg * g_c[ci] + ig * gv;
    g_c[ci] = cn;
    float h = og * tanhf(cn);
    h_out[ci] = h;
    out[((size_t)b * T_ + t) * U_ + u0 + u] = h;
}

// ---------------- launch ------------------------------------------------------
extern "C" void kernel_launch(void* const* d_in, const int* in_sizes, int n_in,
                              void* d_out, int out_size) {
    const float* data = (const float*)d_in[0];   // [32,512,512]
    const float* Wx   = (const float*)d_in[1];   // [512,4096]
    const float* Wh   = (const float*)d_in[2];   // [1024,4096]
    const float* bias = (const float*)d_in[3];   // [4096]
    float* out = (float*)d_out;                  // [32,512,1024]

    init_state<<<32, 1024>>>();

    dim3 grid(G4 / 128, (B_ * T_) / 128);        // 32 x 128
    gemm_xproj<<<grid, 256>>>(data, Wx, bias);

    for (int t = 0; t < T_; t++)
        lstm_step<<<128, 256>>>(Wh, out, t);
}

// round 3
// speedup vs baseline: 1.3223x; 1.1890x over previous
#include <cuda_runtime.h>
#include <math.h>

#define B_   32
#define T_   512
#define IND  512
#define U_   1024
#define G4   4096   // 4*U
#define NBLK 128
#define NTHR 256

// ---------------- scratch (static device globals; no allocs allowed) ----------
__device__ __align__(16) float g_xproj[(size_t)B_ * T_ * G4];  // 256 MB [b*T+t][4U]
__device__ __align__(16) float g_h[2][U_ * B_];                // ping-pong hT: [u][b]
__device__ unsigned g_count;   // barrier arrival counter (self-resetting)
__device__ unsigned g_gen;     // barrier generation (monotonic across replays)

// ---------------- init: zero h0 every launch (graph replays) ------------------
__global__ void init_state() {
    int i = blockIdx.x * blockDim.x + threadIdx.x;
    if (i < U_ * B_) g_h[0][i] = 0.f;
}

// ---------------- Kernel 1: x_proj = data @ Wx + b ----------------------------
__global__ __launch_bounds__(256) void gemm_xproj(
    const float* __restrict__ A, const float* __restrict__ Bw,
    const float* __restrict__ bias)
{
    const int K = IND, N = G4;
    __shared__ float As[16][132];
    __shared__ float Bs[16][128];

    int tid = threadIdx.x;
    int bm = blockIdx.y * 128;
    int bn = blockIdx.x * 128;

    int ty = tid >> 4;
    int tx = tid & 15;

    int arow = tid >> 2;
    int acol = (tid & 3) * 4;
    int brow = tid >> 5;
    int bcol = (tid & 31) * 4;

    const float* Aptr = A + (size_t)(bm + arow) * K + acol;
    const float* Bptr = Bw + (size_t)brow * N + bn + bcol;

    float acc[8][8];
    #pragma unroll
    for (int i = 0; i < 8; i++)
        #pragma unroll
        for (int j = 0; j < 8; j++) acc[i][j] = 0.f;

    for (int k0 = 0; k0 < K; k0 += 16) {
        float4 a0 = *(const float4*)(Aptr);
        float4 a1 = *(const float4*)(Aptr + (size_t)64 * K);
        float4 b0 = *(const float4*)(Bptr);
        float4 b1 = *(const float4*)(Bptr + (size_t)8 * N);

        As[acol + 0][arow] = a0.x; As[acol + 1][arow] = a0.y;
        As[acol + 2][arow] = a0.z; As[acol + 3][arow] = a0.w;
        As[acol + 0][arow + 64] = a1.x; As[acol + 1][arow + 64] = a1.y;
        As[acol + 2][arow + 64] = a1.z; As[acol + 3][arow + 64] = a1.w;
        *(float4*)&Bs[brow][bcol]     = b0;
        *(float4*)&Bs[brow + 8][bcol] = b1;
        __syncthreads();

        #pragma unroll
        for (int kk = 0; kk < 16; kk++) {
            float a[8], b[8];
            *(float4*)&a[0] = *(const float4*)&As[kk][ty * 8];
            *(float4*)&a[4] = *(const float4*)&As[kk][ty * 8 + 4];
            *(float4*)&b[0] = *(const float4*)&Bs[kk][tx * 8];
            *(float4*)&b[4] = *(const float4*)&Bs[kk][tx * 8 + 4];
            #pragma unroll
            for (int i = 0; i < 8; i++)
                #pragma unroll
                for (int j = 0; j < 8; j++)
                    acc[i][j] = fmaf(a[i], b[j], acc[i][j]);
        }
        __syncthreads();
        Aptr += 16;
        Bptr += (size_t)16 * N;
    }

    float bv[8];
    #pragma unroll
    for (int j = 0; j < 8; j++) bv[j] = bias[bn + tx * 8 + j];

    #pragma unroll
    for (int i = 0; i < 8; i++) {
        float* crow = g_xproj + (size_t)(bm + ty * 8 + i) * N + bn + tx * 8;
        float4 v0 = make_float4(acc[i][0] + bv[0], acc[i][1] + bv[1],
                                acc[i][2] + bv[2], acc[i][3] + bv[3]);
        float4 v1 = make_float4(acc[i][4] + bv[4], acc[i][5] + bv[5],
                                acc[i][6] + bv[6], acc[i][7] + bv[7]);
        *(float4*)crow       = v0;
        *(float4*)(crow + 4) = v1;
    }
}

// ---------------- Kernel 2: persistent LSTM recurrence ------------------------
__device__ __forceinline__ float sigmoidf_(float x) {
    return 1.f / (1.f + __expf(-x));
}

#define FMA2(acc, a, b) \
    asm("fma.rn.f32x2 %0, %1, %2, %0;" : "+l"(acc) : "l"(a), "l"(b))
#define DUP32(dst, src) \
    asm("mov.b64 %0, {%1, %1};" : "=l"(dst) : "r"(src))

extern __shared__ float smem_dyn[];

// 128 blocks x 256 threads, all resident (1 block/SM). Block owns 32 Wh columns
// (8 units x 4 gates) pinned in smem. Warp w reduces K-chunk [w*128, +128).
// Lane: g = lane&3 (gate), tb = lane>>2 (4-batch group). Thread accumulates
// 8 units x 4 batches as 16 packed f32x2 registers. c lives in registers.
__global__ __launch_bounds__(NTHR) void lstm_persistent(
    const float* __restrict__ Wh,   // [1024][4096]
    float* __restrict__ out)        // [32][512][1024]
{
    float* ws   = smem_dyn;               // [1024][32]  128 KB
    float* part = smem_dyn + U_ * 32;     // [8][4][8][36] 36 KB

    const int tid  = threadIdx.x;
    const int w    = tid >> 5;
    const int lane = tid & 31;
    const int g    = lane & 3;
    const int tb   = lane >> 2;
    const int u0   = blockIdx.x * 8;

    // ---- load this block's Wh slice into smem (once) ----
    for (int idx = tid; idx < U_ * 8; idx += NTHR) {   // float4 granules
        int k  = idx >> 3;          // row 0..1023
        int r  = idx & 7;
        int g2 = r >> 1;
        int hf = r & 1;
        float4 v = *(const float4*)(Wh + (size_t)k * G4 + g2 * U_ + u0 + hf * 4);
        *(float4*)&ws[k * 32 + g2 * 8 + hf * 4] = v;
    }

    // epilogue identity: fixed (batch, unit) per thread -> c in a register
    const int eb = tid >> 3;
    const int eu = tid & 7;
    float c_reg = 0.f;

    unsigned my_gen = *(volatile unsigned*)&g_gen;  // safe: no bump until all arrive
    __syncthreads();

    const float* wsp_base = ws + (size_t)(w * 128) * 32 + g * 8;

    for (int t = 0; t < T_; t++) {
        const float* __restrict__ h_in = g_h[t & 1];
        float* __restrict__ h_out      = g_h[(t + 1) & 1];

        unsigned long long acc2[4][4];   // [unit-pair][batch]
        #pragma unroll
        for (int i = 0; i < 4; i++)
            #pragma unroll
            for (int j = 0; j < 4; j++) acc2[i][j] = 0ULL;

        const float* wsp = wsp_base;
        const float* hp  = h_in + (w * 128) * B_ + tb * 4;

        #pragma unroll 4
        for (int kk = 0; kk < 128; kk++) {
            ulonglong2 wA = *(const ulonglong2*)(wsp);       // units 0-3
            ulonglong2 wB = *(const ulonglong2*)(wsp + 4);   // units 4-7
            float4 hv = __ldcg((const float4*)hp);           // L2 only (coherent)
            unsigned long long hd0, hd1, hd2, hd3;
            DUP32(hd0, __float_as_uint(hv.x));
            DUP32(hd1, __float_as_uint(hv.y));
            DUP32(hd2, __float_as_uint(hv.z));
            DUP32(hd3, __float_as_uint(hv.w));

            FMA2(acc2[0][0], wA.x, hd0); FMA2(acc2[0][1], wA.x, hd1);
            FMA2(acc2[0][2], wA.x, hd2); FMA2(acc2[0][3], wA.x, hd3);
            FMA2(acc2[1][0], wA.y, hd0); FMA2(acc2[1][1], wA.y, hd1);
            FMA2(acc2[1][2], wA.y, hd2); FMA2(acc2[1][3], wA.y, hd3);
            FMA2(acc2[2][0], wB.x, hd0); FMA2(acc2[2][1], wB.x, hd1);
            FMA2(acc2[2][2], wB.x, hd2); FMA2(acc2[2][3], wB.x, hd3);
            FMA2(acc2[3][0], wB.y, hd0); FMA2(acc2[3][1], wB.y, hd1);
            FMA2(acc2[3][2], wB.y, hd2); FMA2(acc2[3][3], wB.y, hd3);

            wsp += 32;
            hp  += B_;
        }

        // publish partials: part[w][g][u][b] with 36-stride padding
        #pragma unroll
        for (int u2 = 0; u2 < 4; u2++) {
            float lo[4], hi[4];
            #pragma unroll
            for (int j = 0; j < 4; j++) {
                unsigned l32, h32;
                asm("mov.b64 {%0, %1}, %2;" : "=r"(l32), "=r"(h32) : "l"(acc2[u2][j]));
                lo[j] = __uint_as_float(l32);
                hi[j] = __uint_as_float(h32);
            }
            *(float4*)&part[(((w * 4 + g) * 8) + 2 * u2)     * 36 + tb * 4] =
                make_float4(lo[0], lo[1], lo[2], lo[3]);
            *(float4*)&part[(((w * 4 + g) * 8) + 2 * u2 + 1) * 36 + tb * 4] =
                make_float4(hi[0], hi[1], hi[2], hi[3]);
        }
        __syncthreads();

        // ---- epilogue: thread = (eb, eu) ----
        float gate[4];
        #pragma unroll
        for (int g2 = 0; g2 < 4; g2++) {
            float s = 0.f;
            #pragma unroll
            for (int w2 = 0; w2 < 8; w2++)
                s += part[(((w2 * 4 + g2) * 8) + eu) * 36 + eb];
            gate[g2] = s;
        }

        const float* xp = g_xproj + ((size_t)eb * T_ + t) * G4 + u0 + eu;
        gate[0] += xp[0];
        gate[1] += xp[U_];
        gate[2] += xp[2 * U_];
        gate[3] += xp[3 * U_];

        float ig = sigmoidf_(gate[0]);
        float fg = sigmoidf_(gate[1]);
        float gv = tanhf(gate[2]);
        float og = sigmoidf_(gate[3]);

        c_reg = fg * c_reg + ig * gv;
        float h = og * tanhf(c_reg);

        h_out[(u0 + eu) * B_ + eb] = h;
        out[((size_t)eb * T_ + t) * U_ + u0 + eu] = h;

        // ---- grid barrier ----
        __threadfence();          // make h_out/out visible device-wide
        __syncthreads();          // also protects 'part' reuse next step
        if (tid == 0) {
            if (atomicAdd(&g_count, 1u) == NBLK - 1) {
                atomicExch(&g_count, 0u);
                __threadfence();
                atomicAdd(&g_gen, 1u);
            } else {
                while (*(volatile unsigned*)&g_gen == my_gen) {}
            }
            my_gen++;
        }
        __syncthreads();
    }
}

// ---------------- launch ------------------------------------------------------
extern "C" void kernel_launch(void* const* d_in, const int* in_sizes, int n_in,
                              void* d_out, int out_size) {
    const float* data = (const float*)d_in[0];   // [32,512,512]
    const float* Wx   = (const float*)d_in[1];   // [512,4096]
    const float* Wh   = (const float*)d_in[2];   // [1024,4096]
    const float* bias = (const float*)d_in[3];   // [4096]
    float* out = (float*)d_out;                  // [32,512,1024]

    const int smem_bytes = (U_ * 32 + 8 * 4 * 8 * 36) * (int)sizeof(float); // ~165 KB
    cudaFuncSetAttribute(lstm_persistent,
                         cudaFuncAttributeMaxDynamicSharedMemorySize, smem_bytes);

    init_state<<<32, 1024>>>();

    dim3 grid(G4 / 128, (B_ * T_) / 128);        // 32 x 128
    gemm_xproj<<<grid, 256>>>(data, Wx, bias);

    lstm_persistent<<<NBLK, NTHR, smem_bytes>>>(Wh, out);
}

// round 4
// speedup vs baseline: 2.2909x; 1.7325x over previous
#include <cuda_runtime.h>
#include <math.h>

#define B_   32
#define T_   512
#define IND  512
#define U_   1024
#define G4   4096   // 4*U
#define NBLK 128
#define NTHR 256

// ---------------- scratch (static device globals; no allocs allowed) ----------
__device__ __align__(16) float g_xproj[(size_t)B_ * T_ * G4];  // 256 MB [b*T+t][4U]
__device__ __align__(16) float g_h[2][U_ * B_];                // ping-pong hT: [u][b]
__device__ unsigned g_count;   // barrier arrival counter (self-resetting)
__device__ unsigned g_gen;     // barrier generation (monotonic across replays)

// ---------------- init: zero h0 every launch (graph replays) ------------------
__global__ void init_state() {
    int i = blockIdx.x * blockDim.x + threadIdx.x;
    if (i < U_ * B_) g_h[0][i] = 0.f;
}

#define FMA2(acc, a, b) \
    asm("fma.rn.f32x2 %0, %1, %2, %0;" : "+l"(acc) : "l"(a), "l"(b))
#define DUP32(dst, src) \
    asm("mov.b64 %0, {%1, %1};" : "=l"(dst) : "r"(src))
#define UNPK(lo, hi, v) \
    asm("mov.b64 {%0, %1}, %2;" : "=r"(lo), "=r"(hi) : "l"(v))

// ---------------- Kernel 1: x_proj = data @ Wx + b (FFMA2 mainloop) -----------
__global__ __launch_bounds__(256) void gemm_xproj(
    const float* __restrict__ A, const float* __restrict__ Bw,
    const float* __restrict__ bias)
{
    const int K = IND, N = G4;
    __shared__ float As[16][132];   // 528B row stride (16B multiple)
    __shared__ float Bs[16][128];

    int tid = threadIdx.x;
    int bm = blockIdx.y * 128;
    int bn = blockIdx.x * 128;

    int ty = tid >> 4;
    int tx = tid & 15;

    int arow = tid >> 2;
    int acol = (tid & 3) * 4;
    int brow = tid >> 5;
    int bcol = (tid & 31) * 4;

    const float* Aptr = A + (size_t)(bm + arow) * K + acol;
    const float* Bptr = Bw + (size_t)brow * N + bn + bcol;

    unsigned long long acc2[8][4];   // [a-row][b-pair], packed along N
    #pragma unroll
    for (int i = 0; i < 8; i++)
        #pragma unroll
        for (int j = 0; j < 4; j++) acc2[i][j] = 0ULL;

    for (int k0 = 0; k0 < K; k0 += 16) {
        float4 a0 = *(const float4*)(Aptr);
        float4 a1 = *(const float4*)(Aptr + (size_t)64 * K);
        float4 b0 = *(const float4*)(Bptr);
        float4 b1 = *(const float4*)(Bptr + (size_t)8 * N);

        As[acol + 0][arow] = a0.x; As[acol + 1][arow] = a0.y;
        As[acol + 2][arow] = a0.z; As[acol + 3][arow] = a0.w;
        As[acol + 0][arow + 64] = a1.x; As[acol + 1][arow + 64] = a1.y;
        As[acol + 2][arow + 64] = a1.z; As[acol + 3][arow + 64] = a1.w;
        *(float4*)&Bs[brow][bcol]     = b0;
        *(float4*)&Bs[brow + 8][bcol] = b1;
        __syncthreads();

        #pragma unroll
        for (int kk = 0; kk < 16; kk++) {
            float a[8];
            *(float4*)&a[0] = *(const float4*)&As[kk][ty * 8];
            *(float4*)&a[4] = *(const float4*)&As[kk][ty * 8 + 4];
            ulonglong2 bA = *(const ulonglong2*)&Bs[kk][tx * 8];
            ulonglong2 bB = *(const ulonglong2*)&Bs[kk][tx * 8 + 4];
            #pragma unroll
            for (int i = 0; i < 8; i++) {
                unsigned long long ad;
                DUP32(ad, __float_as_uint(a[i]));
                FMA2(acc2[i][0], ad, bA.x);
                FMA2(acc2[i][1], ad, bA.y);
                FMA2(acc2[i][2], ad, bB.x);
                FMA2(acc2[i][3], ad, bB.y);
            }
        }
        __syncthreads();
        Aptr += 16;
        Bptr += (size_t)16 * N;
    }

    float bv[8];
    #pragma unroll
    for (int j = 0; j < 8; j++) bv[j] = bias[bn + tx * 8 + j];

    #pragma unroll
    for (int i = 0; i < 8; i++) {
        float c[8];
        #pragma unroll
        for (int j = 0; j < 4; j++) {
            unsigned lo, hi;
            UNPK(lo, hi, acc2[i][j]);
            c[2 * j]     = __uint_as_float(lo) + bv[2 * j];
            c[2 * j + 1] = __uint_as_float(hi) + bv[2 * j + 1];
        }
        float* crow = g_xproj + (size_t)(bm + ty * 8 + i) * N + bn + tx * 8;
        *(float4*)crow       = make_float4(c[0], c[1], c[2], c[3]);
        *(float4*)(crow + 4) = make_float4(c[4], c[5], c[6], c[7]);
    }
}

// ---------------- Kernel 2: persistent LSTM recurrence ------------------------
__device__ __forceinline__ float sigmoidf_(float x) {
    return 1.f / (1.f + __expf(-x));
}

extern __shared__ float smem_dyn[];

// 128 blocks x 256 threads (1/SM, all resident). Block owns 8 units x 4 gates
// = 32 Wh columns pinned in smem (128 KB). Each step: stage full h (32 KB) into
// smem with front-batched LDG.cg, then pure LDS+FFMA2 inner loop; warp w
// reduces K-chunk [w*128,+128). Partials -> padded smem -> fused epilogue.
__global__ __launch_bounds__(NTHR) void lstm_persistent(
    const float* __restrict__ Wh,   // [1024][4096]
    float* __restrict__ out)        // [32][512][1024]
{
    float* ws   = smem_dyn;                      // [1024][32]  128 KB
    float* hs   = smem_dyn + U_ * 32;            // [1024][32]->this block: [1024 k][32 b]? no: full h 32KB
    float* part = smem_dyn + U_ * 32 + U_ * B_ / 4; // after 8192 floats (32KB)

    // NOTE: hs holds full h for the step: [k=0..1023][b=0..31]? h is [u][b] =
    // 32768 floats = 128KB?? -> h is U_*B_ = 32768 floats = 128 KB. Too big.
    // h layout is [u][b]; we need hs[k][b] for k=0..1023 -> that IS all of h.
    // 32768 floats = 128 KB. ws(128KB)+hs(128KB) > 228KB. So stage only this
    // block's K-range? All warps together need ALL k. Instead: stage h in fp32
    // is 128KB -- cannot. Therefore stage h per-warp-chunk is still all of it.
    // Resolution: hs holds h for ALL k but we drop the 4x batch duplication
    // nothing to drop -- h is 1024x32 floats = 131072 bytes = 128 KB exactly.
    // => reduce ws residency: keep only half of Wh slice in smem (units 0-3),
    // other half streamed? Simpler: keep h staging but halve ws by packing Wh
    // as... fp32 required. Final choice: hs = 32 KB holding h for k in this
    // block's needed range -- but all 1024 k are needed. So: stage h in 4
    // chunks of 256 k (8 KB each) with double buffering? Complexity. Instead
    // we keep h in REGISTERS: each warp needs h[k][tb*4..+3] for its 128 k =
    // 128*4 floats = 16 float4 per lane-group; per thread 16 float4 = 64 regs.
    // Too many. Compromise: prefetch per 32-k subchunk into 16 regs (4 float4)
    // via batched LDG.cg before consuming -- software pipeline with 2 stages.
    (void)hs;

    const int tid  = threadIdx.x;
    const int w    = tid >> 5;
    const int lane = tid & 31;
    const int g    = lane & 3;
    const int tb   = lane >> 2;
    const int u0   = blockIdx.x * 8;

    // ---- load this block's Wh slice into smem (once) ----
    for (int idx = tid; idx < U_ * 8; idx += NTHR) {   // float4 granules
        int k  = idx >> 3;
        int r  = idx & 7;
        int g2 = r >> 1;
        int hf = r & 1;
        float4 v = *(const float4*)(Wh + (size_t)k * G4 + g2 * U_ + u0 + hf * 4);
        *(float4*)&ws[k * 32 + g2 * 8 + hf * 4] = v;
    }

    const int eb = tid >> 3;
    const int eu = tid & 7;
    float c_reg = 0.f;

    unsigned my_gen = *(volatile unsigned*)&g_gen;
    __syncthreads();

    const float* wsp_base = ws + (size_t)(w * 128) * 32 + g * 8;

    for (int t = 0; t < T_; t++) {
        const float* __restrict__ h_in = g_h[t & 1];
        float* __restrict__ h_out      = g_h[(t + 1) & 1];

        // prefetch this thread's x_proj values (DRAM) early
        const float* xp = g_xproj + ((size_t)eb * T_ + t) * G4 + u0 + eu;
        float xpv0 = __ldg(xp);
        float xpv1 = __ldg(xp + U_);
        float xpv2 = __ldg(xp + 2 * U_);
        float xpv3 = __ldg(xp + 3 * U_);

        unsigned long long acc2[4][4];   // [unit-pair][batch]
        #pragma unroll
        for (int i = 0; i < 4; i++)
            #pragma unroll
            for (int j = 0; j < 4; j++) acc2[i][j] = 0ULL;

        const float* wsp = wsp_base;
        const float4* hp = (const float4*)(h_in + (w * 128) * B_) + tb;

        // software-pipelined: prefetch h for 8-k groups (8 float4) ahead
        float4 hbuf[8];
        #pragma unroll
        for (int i = 0; i < 8; i++) hbuf[i] = __ldcg(hp + i * 8);

        #pragma unroll 2
        for (int kg = 0; kg < 16; kg++) {          // 16 groups of 8 k
            float4 hnext[8];
            if (kg < 15) {
                #pragma unroll
                for (int i = 0; i < 8; i++)
                    hnext[i] = __ldcg(hp + (kg + 1) * 64 + i * 8);
            }
            #pragma unroll
            for (int kk = 0; kk < 8; kk++) {
                ulonglong2 wA = *(const ulonglong2*)(wsp + kk * 32);
                ulonglong2 wB = *(const ulonglong2*)(wsp + kk * 32 + 4);
                float4 hv = hbuf[kk];
                unsigned long long hd0, hd1, hd2, hd3;
                DUP32(hd0, __float_as_uint(hv.x));
                DUP32(hd1, __float_as_uint(hv.y));
                DUP32(hd2, __float_as_uint(hv.z));
                DUP32(hd3, __float_as_uint(hv.w));

                FMA2(acc2[0][0], wA.x, hd0); FMA2(acc2[0][1], wA.x, hd1);
                FMA2(acc2[0][2], wA.x, hd2); FMA2(acc2[0][3], wA.x, hd3);
                FMA2(acc2[1][0], wA.y, hd0); FMA2(acc2[1][1], wA.y, hd1);
                FMA2(acc2[1][2], wA.y, hd2); FMA2(acc2[1][3], wA.y, hd3);
                FMA2(acc2[2][0], wB.x, hd0); FMA2(acc2[2][1], wB.x, hd1);
                FMA2(acc2[2][2], wB.x, hd2); FMA2(acc2[2][3], wB.x, hd3);
                FMA2(acc2[3][0], wB.y, hd0); FMA2(acc2[3][1], wB.y, hd1);
                FMA2(acc2[3][2], wB.y, hd2); FMA2(acc2[3][3], wB.y, hd3);
            }
            #pragma unroll
            for (int i = 0; i < 8; i++) hbuf[i] = hnext[i];
            wsp += 8 * 32;
        }

        // publish partials: part[w][g][u][b], 36-stride padding
        #pragma unroll
        for (int u2 = 0; u2 < 4; u2++) {
            float lo[4], hi[4];
            #pragma unroll
            for (int j = 0; j < 4; j++) {
                unsigned l32, h32;
                UNPK(l32, h32, acc2[u2][j]);
                lo[j] = __uint_as_float(l32);
                hi[j] = __uint_as_float(h32);
            }
            *(float4*)&part[(((w * 4 + g) * 8) + 2 * u2)     * 36 + tb * 4] =
                make_float4(lo[0], lo[1], lo[2], lo[3]);
            *(float4*)&part[(((w * 4 + g) * 8) + 2 * u2 + 1) * 36 + tb * 4] =
                make_float4(hi[0], hi[1], hi[2], hi[3]);
        }
        __syncthreads();

        // ---- epilogue: thread = (eb, eu) ----
        float gate[4];
        #pragma unroll
        for (int g2 = 0; g2 < 4; g2++) {
            float s = 0.f;
            #pragma unroll
            for (int w2 = 0; w2 < 8; w2++)
                s += part[(((w2 * 4 + g2) * 8) + eu) * 36 + eb];
            gate[g2] = s;
        }
        gate[0] += xpv0;
        gate[1] += xpv1;
        gate[2] += xpv2;
        gate[3] += xpv3;

        float ig = sigmoidf_(gate[0]);
        float fg = sigmoidf_(gate[1]);
        float gv = tanhf(gate[2]);
        float og = sigmoidf_(gate[3]);

        c_reg = fg * c_reg + ig * gv;
        float h = og * tanhf(c_reg);

        h_out[(u0 + eu) * B_ + eb] = h;
        out[((size_t)eb * T_ + t) * U_ + u0 + eu] = h;

        // ---- grid barrier (cooperative-groups pattern: 1 fence per block) ----
        __syncthreads();
        if (tid == 0) {
            __threadfence();
            if (atomicAdd(&g_count, 1u) == NBLK - 1) {
                atomicExch(&g_count, 0u);
                __threadfence();
                atomicAdd(&g_gen, 1u);
            } else {
                while (*(volatile unsigned*)&g_gen == my_gen) {}
            }
            my_gen++;
        }
        __syncthreads();
    }
}

// ---------------- launch ------------------------------------------------------
extern "C" void kernel_launch(void* const* d_in, const int* in_sizes, int n_in,
                              void* d_out, int out_size) {
    const float* data = (const float*)d_in[0];   // [32,512,512]
    const float* Wx   = (const float*)d_in[1];   // [512,4096]
    const float* Wh   = (const float*)d_in[2];   // [1024,4096]
    const float* bias = (const float*)d_in[3];   // [4096]
    float* out = (float*)d_out;                  // [32,512,1024]

    const int smem_bytes =
        (U_ * 32 + U_ * B_ / 4 + 8 * 4 * 8 * 36) * (int)sizeof(float); // ~197 KB
    cudaFuncSetAttribute(lstm_persistent,
                         cudaFuncAttributeMaxDynamicSharedMemorySize, smem_bytes);

    init_state<<<32, 1024>>>();

    dim3 grid(G4 / 128, (B_ * T_) / 128);        // 32 x 128
    gemm_xproj<<<grid, 256>>>(data, Wx, bias);

    lstm_persistent<<<NBLK, NTHR, smem_bytes>>>(Wh, out);
}